// round 13
// baseline (speedup 1.0000x reference)
#include <cuda_runtime.h>
#include <math_constants.h>

#define BB 32
#define SS 4096
#define HH 1024
#define KSPLIT 16
#define KCH (HH / KSPLIT)   // 64
#define BG 8                 // batches per v-worker block
#define NBG (BB / BG)        // 4 batch groups
#define HTW 256
#define NVBLK 256            // v-worker blocks (lbid < NVBLK)

// Scratch (allocation-free rule: __device__ globals; zero-initialized)
__device__ float g_vp[KSPLIT][BB * HH];   // split-K partials (2 MB)
__device__ float g_v[BB * HH];            // reduced v
__device__ unsigned int g_bgcnt[NBG];     // per-batch-group partials counters
__device__ unsigned int g_ready[BB];      // per-batch v-ready flags

__device__ __forceinline__ unsigned int ld_acq(const unsigned int* p) {
    unsigned int v;
    asm volatile("ld.acquire.gpu.u32 %0, [%1];" : "=r"(v) : "l"(p) : "memory");
    return v;
}
__device__ __forceinline__ void st_rel(unsigned int* p, unsigned int v) {
    asm volatile("st.release.gpu.u32 [%0], %1;" :: "l"(p), "r"(v) : "memory");
}

// ---------------------------------------------------------------------------
// Fused kernel: grid (128, 32) x 256 thr, capped 5 blocks/SM (<=51 regs).
// R13 fixes: R11's reg coupling (66-reg v shape) replaced by the low-reg
// BG=8 shape (~45 regs) so the score phase keeps 40 warps/SM (R1 achieved
// only ~36). Per-batch-GROUP counters stagger readiness: batches 0-7 unlock
// while groups 1-3 still compute -> v work hides under the enc-stream ramp.
//  lbid < 256 : v partials for 8 batches      (bg = lbid>>6)
//  lbid < 32  : then reduce batch lbid, st.release g_ready[lbid]
//  everyone   : spin only on g_ready[own b], then R1's proven score loop.
// bias dropped: softmax is shift-invariant. No prefetch (R10 lesson).
// ---------------------------------------------------------------------------
__global__ void __launch_bounds__(256, 5) fused_k(const float* __restrict__ hidden,
                                                  const float* __restrict__ W,
                                                  const float* __restrict__ enc,
                                                  float* __restrict__ out) {
    __shared__ float4 sv[HH / 4];           // staged v[b] for score phase
    __shared__ float sh[BG * KCH];          // staged hidden for v phase (2 KB)

    const int b   = blockIdx.y;
    const int tid = threadIdx.x;
    const unsigned int lbid = blockIdx.x + gridDim.x * blockIdx.y;

    if (lbid < NVBLK) {
        // ---------------- v partial phase (low-reg BG=8 shape) ----------------
        const int hx = lbid & 3;
        const int ks = (lbid >> 2) & (KSPLIT - 1);
        const int bg = lbid >> 6;            // 0..3
        const int k0 = ks * KCH;
        const int h  = hx * HTW + tid;

        for (int i = tid; i < BG * KCH; i += 256) {
            int j = i / KCH, k = i % KCH;
            sh[i] = hidden[(bg * BG + j) * HH + k0 + k];
        }
        __syncthreads();

        float acc[BG];
        #pragma unroll
        for (int j = 0; j < BG; j++) acc[j] = 0.f;

        #pragma unroll
        for (int kk = 0; kk < KCH; kk += 16) {
            float wv[16];
            #pragma unroll
            for (int u = 0; u < 16; u++)
                wv[u] = W[(size_t)(k0 + kk + u) * HH + h];
            #pragma unroll
            for (int u = 0; u < 16; u++)
                #pragma unroll
                for (int j = 0; j < BG; j++)
                    acc[j] += sh[j * KCH + kk + u] * wv[u];
        }
        #pragma unroll
        for (int j = 0; j < BG; j++)
            g_vp[ks][(bg * BG + j) * HH + h] = acc[j];

        __threadfence();
        __syncthreads();
        if (tid == 0) atomicAdd(&g_bgcnt[bg], 1u);   // 64 workers per bg

        if (lbid < BB) {
            // ---- reducer for batch r = lbid: wait only its own group ----
            const int r = lbid;
            const int rg = r >> 3;                   // r's batch group
            if (tid == 0) {
                while (ld_acq(&g_bgcnt[rg]) < 64u) __nanosleep(64);
            }
            __syncthreads();
            #pragma unroll
            for (int j = 0; j < 4; j++) {
                const int idx = r * HH + tid + j * 256;
                float s = 0.f;
                #pragma unroll
                for (int p = 0; p < KSPLIT; p++) s += __ldcg(&g_vp[p][idx]);
                g_v[idx] = s;
            }
            __threadfence();
            __syncthreads();
            if (tid == 0) st_rel(&g_ready[r], 1u);
        }
    }

    // ---------------- wait only for our own batch's v ----------------
    if (tid == 0) {
        while (ld_acq(&g_ready[b]) == 0u) __nanosleep(64);
    }
    __syncthreads();

    // ---------------- score phase: exact R1 structure ----------------
    for (int i = tid; i < HH / 4; i += 256)
        sv[i] = reinterpret_cast<const float4*>(g_v + b * HH)[i];
    __syncthreads();

    const int w = tid >> 5, lane = tid & 31;
    const int s0 = blockIdx.x * 32 + w * 4;

    #pragma unroll
    for (int r = 0; r < 4; r++) {
        const int s = s0 + r;
        const float4* row =
            reinterpret_cast<const float4*>(enc + (size_t)b * SS * HH + (size_t)s * HH);
        float acc = 0.f;
        #pragma unroll
        for (int i = 0; i < 8; i++) {
            float4 e = row[lane + i * 32];
            float4 v = sv[lane + i * 32];
            acc += e.x * v.x + e.y * v.y + e.z * v.z + e.w * v.w;
        }
        #pragma unroll
        for (int o = 16; o; o >>= 1) acc += __shfl_xor_sync(0xffffffffu, acc, o);
        if (lane == 0) out[b * SS + s] = acc;
    }
}

// ---------------------------------------------------------------------------
// Softmax in place over each row of 4096. grid BB, block 1024.
// Also resets fused_k's sync words for the next graph replay.
// ---------------------------------------------------------------------------
__global__ void softmax_k(float* __restrict__ out) {
    __shared__ float red[32];
    __shared__ float bcast;
    if (blockIdx.x == 0) {
        if (threadIdx.x < NBG) g_bgcnt[threadIdx.x] = 0u;
        if (threadIdx.x >= 32 && threadIdx.x < 32 + BB)
            g_ready[threadIdx.x - 32] = 0u;
    }
    float* row = out + blockIdx.x * SS;
    const int w = threadIdx.x >> 5, lane = threadIdx.x & 31;

    float vals[4];
    float mx = -CUDART_INF_F;
    #pragma unroll
    for (int i = 0; i < 4; i++) {
        vals[i] = row[threadIdx.x + i * 1024];
        mx = fmaxf(mx, vals[i]);
    }
    #pragma unroll
    for (int o = 16; o; o >>= 1) mx = fmaxf(mx, __shfl_xor_sync(0xffffffffu, mx, o));
    if (lane == 0) red[w] = mx;
    __syncthreads();
    if (w == 0) {
        float m = red[lane];
        #pragma unroll
        for (int o = 16; o; o >>= 1) m = fmaxf(m, __shfl_xor_sync(0xffffffffu, m, o));
        if (lane == 0) bcast = m;
    }
    __syncthreads();
    mx = bcast;

    float sum = 0.f;
    #pragma unroll
    for (int i = 0; i < 4; i++) {
        vals[i] = __expf(vals[i] - mx);
        sum += vals[i];
    }
    #pragma unroll
    for (int o = 16; o; o >>= 1) sum += __shfl_xor_sync(0xffffffffu, sum, o);
    if (lane == 0) red[w] = sum;
    __syncthreads();
    if (w == 0) {
        float s = red[lane];
        #pragma unroll
        for (int o = 16; o; o >>= 1) s += __shfl_xor_sync(0xffffffffu, s, o);
        if (lane == 0) bcast = s;
    }
    __syncthreads();
    const float inv = 1.0f / bcast;

    #pragma unroll
    for (int i = 0; i < 4; i++)
        row[threadIdx.x + i * 1024] = vals[i] * inv;
}

extern "C" void kernel_launch(void* const* d_in, const int* in_sizes, int n_in,
                              void* d_out, int out_size) {
    const float* hidden = (const float*)d_in[0];  // [B,1,H]
    const float* enc    = (const float*)d_in[1];  // [B,S,H]
    const float* W      = (const float*)d_in[2];  // [H,H]
    // d_in[3] = bias — unused: constant per row under softmax
    float* out = (float*)d_out;                   // [B,S]

    fused_k<<<dim3(SS / 32, BB), 256>>>(hidden, W, enc, out);
    softmax_k<<<BB, 1024>>>(out);
}

// round 14
// speedup vs baseline: 1.0226x; 1.0226x over previous
#include <cuda_runtime.h>
#include <math_constants.h>

#define BB 32
#define SS 4096
#define HH 1024
#define KSPLIT 64
#define KCH (HH / KSPLIT)   // 16
#define HX 4
#define HTW 256

// Scratch (allocation-free rule: __device__ globals; zero-initialized)
__device__ float g_vp[KSPLIT][BB * HH];   // split-K partials (8 MB)
__device__ float g_v[BB * HH];            // reduced v
__device__ unsigned int g_vcnt[HX];       // partials-complete counters
__device__ unsigned int g_vdone[HX];      // reduction-complete counters
__device__ unsigned int g_allv;           // "v fully done" flag (prefetch gate)

__device__ __forceinline__ void prefetch_l2(const void* p) {
    asm volatile("prefetch.global.L2 [%0];" :: "l"(p));
}

// ---------------------------------------------------------------------------
// v = hid @ W (R9 shape — best measured). Split-K partials + spin reduction.
// grid (4, 64) = 256 blocks x 256 thr, all resident -> spin cannot deadlock.
// PDL: trigger fires after partial stores, so score_k's grid launches while
// the reduce/spin tail still runs. bias dropped (softmax shift-invariant).
// ---------------------------------------------------------------------------
__global__ void __launch_bounds__(256) v_k(const float* __restrict__ hidden,
                                           const float* __restrict__ W) {
    __shared__ float sh[KCH * BB];  // [k][b], 2 KB
    const int hx = blockIdx.x;
    const int ks = blockIdx.y;
    const int k0 = ks * KCH;
    const int h  = hx * HTW + threadIdx.x;

    for (int i = threadIdx.x; i < KCH * BB; i += 256) {
        int k = i / BB, b = i % BB;
        sh[i] = hidden[b * HH + k0 + k];
    }
    __syncthreads();

    float wv[KCH];
    #pragma unroll
    for (int u = 0; u < KCH; u++)
        wv[u] = W[(size_t)(k0 + u) * HH + h];

    float acc[BB];
    #pragma unroll
    for (int b = 0; b < BB; b++) acc[b] = 0.f;

    #pragma unroll
    for (int u = 0; u < KCH; u++) {
        const float4* hb4 = reinterpret_cast<const float4*>(&sh[u * BB]);
        #pragma unroll
        for (int j = 0; j < BB / 4; j++) {
            float4 hv = hb4[j];                       // broadcast LDS.128
            acc[j * 4 + 0] += hv.x * wv[u];
            acc[j * 4 + 1] += hv.y * wv[u];
            acc[j * 4 + 2] += hv.z * wv[u];
            acc[j * 4 + 3] += hv.w * wv[u];
        }
    }
    #pragma unroll
    for (int b = 0; b < BB; b++)
        g_vp[ks][b * HH + h] = acc[b];

    __threadfence();
    __syncthreads();

    // Partials stored: let the dependent score_k grid start launching now.
    if (threadIdx.x == 0) cudaTriggerProgrammaticLaunchCompletion();

    if (threadIdx.x == 0) {
        atomicAdd(&g_vcnt[hx], 1u);
        unsigned int c;
        do {
            asm volatile("ld.acquire.gpu.u32 %0, [%1];"
                         : "=r"(c) : "l"(&g_vcnt[hx]) : "memory");
            if (c < KSPLIT) __nanosleep(64);
        } while (c < KSPLIT);
    }
    __syncthreads();

    if (ks < BB) {
        const int idx = ks * HH + h;
        float s = 0.f;
        #pragma unroll
        for (int p = 0; p < KSPLIT; p++) s += __ldcg(&g_vp[p][idx]);
        g_v[idx] = s;
        __threadfence();
    }

    __syncthreads();
    if (threadIdx.x == 0) {
        if (atomicAdd(&g_vdone[hx], 1u) == KSPLIT - 1u) {
            g_vcnt[hx] = 0u;
            g_vdone[hx] = 0u;
            // benign-racy completion flag (gates score_k's prefetch only)
            atomicAdd(&g_allv, 1u);
        }
    }
}

// ---------------------------------------------------------------------------
// Energies — R1 structure, launched via PDL. Blocks scheduled while v_k's
// tail runs prefetch their own enc tile into L2 (gated: skipped once v is
// done, so late waves don't duplicate work — the R10 defect). Then a HW
// grid-dependency wait (no spin) before reading g_v.
// grid (SS/32, BB) = (128, 32), block 256 = 8 warps x 4 rows/warp.
// ---------------------------------------------------------------------------
__global__ void __launch_bounds__(256) score_k(const float* __restrict__ enc,
                                               float* __restrict__ out) {
    __shared__ float4 sv[HH / 4];  // v[b] staged, 4 KB
    const int b = blockIdx.y;
    const float* my_enc = enc + (size_t)b * SS * HH + (size_t)blockIdx.x * 32 * HH;

    unsigned int vdone;
    asm volatile("ld.global.cg.u32 %0, [%1];" : "=r"(vdone) : "l"(&g_allv));
    if (vdone < HX) {
        // v still in flight: warm L2 with this block's own 128 KB tile.
        for (int i = threadIdx.x; i < 1024; i += 256)
            prefetch_l2(my_enc + i * 32);          // one 128B line each
    }

    cudaGridDependencySynchronize();               // HW wait for v_k grid

    for (int i = threadIdx.x; i < HH / 4; i += 256)
        sv[i] = reinterpret_cast<const float4*>(g_v + b * HH)[i];
    __syncthreads();

    const int w = threadIdx.x >> 5, lane = threadIdx.x & 31;
    const int s0 = blockIdx.x * 32 + w * 4;

    #pragma unroll
    for (int r = 0; r < 4; r++) {
        const int s = s0 + r;
        const float4* row =
            reinterpret_cast<const float4*>(enc + (size_t)b * SS * HH + (size_t)s * HH);
        float acc = 0.f;
        #pragma unroll
        for (int i = 0; i < 8; i++) {
            float4 e = row[lane + i * 32];
            float4 v = sv[lane + i * 32];
            acc += e.x * v.x + e.y * v.y + e.z * v.z + e.w * v.w;
        }
        #pragma unroll
        for (int o = 16; o; o >>= 1) acc += __shfl_xor_sync(0xffffffffu, acc, o);
        if (lane == 0) out[b * SS + s] = acc;
    }
}

// ---------------------------------------------------------------------------
// Softmax in place over each row of 4096. grid BB, block 1024. PDL: launches
// early, HW-waits for score_k, then runs. Resets g_allv for next replay.
// ---------------------------------------------------------------------------
__global__ void softmax_k(float* __restrict__ out) {
    __shared__ float red[32];
    __shared__ float bcast;

    cudaGridDependencySynchronize();               // HW wait for score_k grid
    if (blockIdx.x == 0 && threadIdx.x == 0) g_allv = 0u;

    float* row = out + blockIdx.x * SS;
    const int w = threadIdx.x >> 5, lane = threadIdx.x & 31;

    float vals[4];
    float mx = -CUDART_INF_F;
    #pragma unroll
    for (int i = 0; i < 4; i++) {
        vals[i] = row[threadIdx.x + i * 1024];
        mx = fmaxf(mx, vals[i]);
    }
    #pragma unroll
    for (int o = 16; o; o >>= 1) mx = fmaxf(mx, __shfl_xor_sync(0xffffffffu, mx, o));
    if (lane == 0) red[w] = mx;
    __syncthreads();
    if (w == 0) {
        float m = red[lane];
        #pragma unroll
        for (int o = 16; o; o >>= 1) m = fmaxf(m, __shfl_xor_sync(0xffffffffu, m, o));
        if (lane == 0) bcast = m;
    }
    __syncthreads();
    mx = bcast;

    float sum = 0.f;
    #pragma unroll
    for (int i = 0; i < 4; i++) {
        vals[i] = __expf(vals[i] - mx);
        sum += vals[i];
    }
    #pragma unroll
    for (int o = 16; o; o >>= 1) sum += __shfl_xor_sync(0xffffffffu, sum, o);
    if (lane == 0) red[w] = sum;
    __syncthreads();
    if (w == 0) {
        float s = red[lane];
        #pragma unroll
        for (int o = 16; o; o >>= 1) s += __shfl_xor_sync(0xffffffffu, s, o);
        if (lane == 0) bcast = s;
    }
    __syncthreads();
    const float inv = 1.0f / bcast;

    #pragma unroll
    for (int i = 0; i < 4; i++)
        row[threadIdx.x + i * 1024] = vals[i] * inv;
}

extern "C" void kernel_launch(void* const* d_in, const int* in_sizes, int n_in,
                              void* d_out, int out_size) {
    const float* hidden = (const float*)d_in[0];  // [B,1,H]
    const float* enc    = (const float*)d_in[1];  // [B,S,H]
    const float* W      = (const float*)d_in[2];  // [H,H]
    // d_in[3] = bias — unused: constant per row under softmax
    float* out = (float*)d_out;                   // [B,S]

    // 1) v_k: plain launch (primary of the first PDL edge)
    v_k<<<dim3(HX, KSPLIT), 256>>>(hidden, W);

    // 2) score_k: programmatic dependent launch on v_k
    {
        cudaLaunchConfig_t cfg = {};
        cfg.gridDim  = dim3(SS / 32, BB);
        cfg.blockDim = dim3(256);
        cudaLaunchAttribute attr[1];
        attr[0].id = cudaLaunchAttributeProgrammaticStreamSerialization;
        attr[0].val.programmaticStreamSerializationAllowed = 1;
        cfg.attrs = attr;
        cfg.numAttrs = 1;
        cudaLaunchKernelEx(&cfg, score_k, enc, out);
    }

    // 3) softmax_k: programmatic dependent launch on score_k
    {
        cudaLaunchConfig_t cfg = {};
        cfg.gridDim  = dim3(BB);
        cfg.blockDim = dim3(1024);
        cudaLaunchAttribute attr[1];
        attr[0].id = cudaLaunchAttributeProgrammaticStreamSerialization;
        attr[0].val.programmaticStreamSerializationAllowed = 1;
        cfg.attrs = attr;
        cfg.numAttrs = 1;
        cudaLaunchKernelEx(&cfg, softmax_k, out);
    }
}